// round 1
// baseline (speedup 1.0000x reference)
#include <cuda_runtime.h>
#include <math.h>

#define Bn   128
#define Hn   8
#define Rn   130
#define Tn   256
#define Qd   32
#define BHn  (Bn*Hn)     /* 1024 */
#define Mn   (Bn*Rn)     /* 16640 */
#define NQK  512

// ---------------- device scratch (no allocations allowed) ----------------
__device__ float g_qk[(size_t)Mn*NQK];            // q|k projections, [M,512]
__device__ float g_feats[(size_t)BHn*Rn*Tn];      // GCN features (flagged heads only)
__device__ float g_agg[(size_t)BHn*Rn*Tn];        // sparse A @ feats scratch
__device__ float g_spval[BHn*Rn*8];               // sparse A values (pre-gate)
__device__ int   g_spcol[BHn*Rn*8];               // sparse A column indices
__device__ int   g_spcnt[BHn*Rn];                 // nnz per row (6 or 7)
__device__ float g_gap[BHn];                      // sum of rel per (b,h)
__device__ float g_maxA[BHn];                     // max kept rel value per (b,h)
__device__ float g_gate[BHn];                     // SE gate (0 or 1)
__device__ int   g_flag[BHn];                     // gate!=0 && maxA>0
__device__ float g_S[Tn+1];                       // S[t]=sum_i relu(gcn_b[i][t]); S[256]=mean

// ---------------- K1: qk = x @ [Wq;Wk]^T + [bq;bk] -----------------------
// M=16640, K=256, N=512. 64x64 tile, BK=16, 256 threads, 4x4 per thread.
__global__ void k_qkproj(const float* __restrict__ x,
                         const float* __restrict__ Wq, const float* __restrict__ bq,
                         const float* __restrict__ Wk, const float* __restrict__ bk)
{
    __shared__ float As[16][68];
    __shared__ float Bs[16][68];
    int tid = threadIdx.x;
    int m0 = blockIdx.x * 64, n0 = blockIdx.y * 64;
    int lr  = tid >> 2;          // 0..63
    int lc4 = (tid & 3) * 4;     // 0,4,8,12
    int tm  = (tid >> 4) * 4, tn = (tid & 15) * 4;
    float acc[4][4] = {};

    for (int k0 = 0; k0 < 256; k0 += 16) {
        float4 av = *(const float4*)(x + (size_t)(m0 + lr) * 256 + k0 + lc4);
        As[lc4+0][lr] = av.x; As[lc4+1][lr] = av.y;
        As[lc4+2][lr] = av.z; As[lc4+3][lr] = av.w;
        int ng = n0 + lr;
        const float* wrow = (ng < 256) ? (Wq + (size_t)ng * 256)
                                       : (Wk + (size_t)(ng - 256) * 256);
        float4 bv = *(const float4*)(wrow + k0 + lc4);
        Bs[lc4+0][lr] = bv.x; Bs[lc4+1][lr] = bv.y;
        Bs[lc4+2][lr] = bv.z; Bs[lc4+3][lr] = bv.w;
        __syncthreads();
        #pragma unroll
        for (int kk = 0; kk < 16; kk++) {
            float a[4], bb[4];
            #pragma unroll
            for (int i = 0; i < 4; i++) a[i]  = As[kk][tm + i];
            #pragma unroll
            for (int j = 0; j < 4; j++) bb[j] = Bs[kk][tn + j];
            #pragma unroll
            for (int i = 0; i < 4; i++)
                #pragma unroll
                for (int j = 0; j < 4; j++)
                    acc[i][j] = fmaf(a[i], bb[j], acc[i][j]);
        }
        __syncthreads();
    }
    #pragma unroll
    for (int j = 0; j < 4; j++) {
        int n = n0 + tn + j;
        float bias = (n < 256) ? bq[n] : bk[n - 256];
        #pragma unroll
        for (int i = 0; i < 4; i++)
            g_qk[(size_t)(m0 + tm + i) * NQK + n] = acc[i][j] + bias;
    }
}

// ---------------- K2: rel -> softmax -> relu-thr -> ranks/sparse ---------
#define SQS  33
#define RELS 132
__global__ void k_attn(const float* __restrict__ thr_p)
{
    extern __shared__ float sm[];
    float* sq   = sm;                   // 130*33
    float* sk   = sm +     Rn * SQS;    // 130*33
    float* srel = sm + 2 * Rn * SQS;    // 130*132
    __shared__ float s_gap[8], s_max[8];

    int bh = blockIdx.x, b = bh >> 3, h = bh & 7;
    int tid = threadIdx.x, lane = tid & 31, w = tid >> 5;
    const float thr = *thr_p;

    for (int e = tid; e < Rn * Qd; e += 256) {
        int r = e >> 5, i = e & 31;
        size_t rowb = (size_t)(b * Rn + r) * NQK + h * 32;
        sq[r * SQS + i] = g_qk[rowb + i];
        sk[r * SQS + i] = g_qk[rowb + 256 + i];
    }
    __syncthreads();

    for (int e = tid; e < Rn * Rn; e += 256) {
        int r = e / Rn, s = e - r * Rn;
        float acc = 0.f;
        #pragma unroll
        for (int i = 0; i < 32; i++)
            acc = fmaf(sq[r * SQS + i], sk[s * SQS + i], acc);
        srel[r * RELS + s] = acc * 0.17677669529663687f;  // 1/sqrt(32)
    }
    __syncthreads();

    float gapAcc = 0.f, maxAcc = 0.f;
    for (int r = w; r < Rn; r += 8) {
        float* row = srel + r * RELS;
        float mval = -1e30f;
        for (int j = lane; j < Rn; j += 32) mval = fmaxf(mval, row[j]);
        #pragma unroll
        for (int o = 16; o; o >>= 1) mval = fmaxf(mval, __shfl_xor_sync(~0u, mval, o));
        float se = 0.f;
        for (int j = lane; j < Rn; j += 32) {
            float e = __expf(row[j] - mval); row[j] = e; se += e;
        }
        #pragma unroll
        for (int o = 16; o; o >>= 1) se += __shfl_xor_sync(~0u, se, o);
        float rinv = 1.f / se;
        float gs = 0.f;
        for (int j = lane; j < Rn; j += 32) {
            float v = fmaxf(fmaf(row[j], rinv, -thr), 0.f);
            row[j] = v; gs += v;
        }
        #pragma unroll
        for (int o = 16; o; o >>= 1) gs += __shfl_xor_sync(~0u, gs, o);
        __syncwarp();

        // ranks (stable descending) of columns {0, 4..8}
        const int cols0[6] = {0, 4, 5, 6, 7, 8};
        float vc[6];
        #pragma unroll
        for (int c = 0; c < 6; c++) vc[c] = row[cols0[c]];
        int gt[6] = {0,0,0,0,0,0}, eqb[6] = {0,0,0,0,0,0};
        for (int j0 = 0; j0 < Rn; j0 += 32) {
            int j = j0 + lane; bool val = (j < Rn);
            float vj = val ? row[j] : 0.f;
            #pragma unroll
            for (int c = 0; c < 6; c++) {
                unsigned bgt = __ballot_sync(~0u, val && (vj > vc[c]));
                unsigned beq = __ballot_sync(~0u, val && (vj == vc[c]) && (j < cols0[c]));
                gt[c]  += __popc(bgt);
                eqb[c] += __popc(beq);
            }
        }
        if (lane == 0) {
            gapAcc += gs;
            int pos[7]; int cnt = 0;
            #pragma unroll
            for (int c = 0; c < 6; c++) pos[cnt++] = gt[c] + eqb[c];
            bool hasR = false;
            #pragma unroll
            for (int c = 0; c < 6; c++) if (pos[c] == r) hasR = true;
            if (!hasR) pos[cnt++] = r;
            int base = (bh * Rn + r) * 8;
            float rmax = 0.f;
            for (int c = 0; c < cnt; c++) {
                float v = row[pos[c]];
                g_spcol[base + c] = pos[c];
                g_spval[base + c] = v;
                rmax = fmaxf(rmax, v);
            }
            g_spcnt[bh * Rn + r] = cnt;
            maxAcc = fmaxf(maxAcc, rmax);
        }
    }
    if (lane == 0) { s_gap[w] = gapAcc; s_max[w] = maxAcc; }
    __syncthreads();
    if (tid == 0) {
        float g = 0.f, mx = 0.f;
        #pragma unroll
        for (int i = 0; i < 8; i++) { g += s_gap[i]; mx = fmaxf(mx, s_max[i]); }
        g_gap[bh] = g; g_maxA[bh] = mx;
    }
}

// ---------------- K3: SE gate + flags -------------------------------------
__global__ void k_gate(const float* __restrict__ seW1, const float* __restrict__ seb1,
                       const float* __restrict__ seW2, const float* __restrict__ seb2)
{
    int b = blockIdx.x;
    if (threadIdx.x) return;
    float g[8];
    #pragma unroll
    for (int h = 0; h < 8; h++) g[h] = g_gap[b * 8 + h] * (1.f / 16900.f);
    float hd[4];
    #pragma unroll
    for (int j = 0; j < 4; j++) {
        float a = seb1[j];
        #pragma unroll
        for (int h = 0; h < 8; h++) a = fmaf(seW1[j * 8 + h], g[h], a);
        hd[j] = fmaxf(a, 0.f);
    }
    #pragma unroll
    for (int i = 0; i < 8; i++) {
        float z = seb2[i];
        #pragma unroll
        for (int j = 0; j < 4; j++) z = fmaf(seW2[i * 4 + j], hd[j], z);
        float gt = floorf(1.f / (1.f + expf(-z)));   // .long() truncation
        g_gate[b * 8 + i] = gt;
        g_flag[b * 8 + i] = (gt != 0.f) && (g_maxA[b * 8 + i] > 0.f);
    }
}

// ---------------- Kprep: S[t] = sum_i relu(gcn_b[i][t]) -------------------
__global__ void k_prep(const float* __restrict__ gcn_b)
{
    __shared__ float red[256];
    int t = threadIdx.x;
    float s = 0.f;
    #pragma unroll
    for (int i = 0; i < 8; i++) s += fmaxf(gcn_b[i * 256 + t], 0.f);
    g_S[t] = s;
    red[t] = s; __syncthreads();
    for (int o = 128; o; o >>= 1) { if (t < o) red[t] += red[t + o]; __syncthreads(); }
    if (t == 0) g_S[256] = red[0] * (1.f / 256.f);
}

// ---------------- GCN path (flag-guarded; empty on degenerate input) ------
__global__ void k_finit(const float* __restrict__ x)
{
    int bh = blockIdx.x;
    if (!g_flag[bh]) return;
    int b = bh >> 3;
    size_t base = (size_t)bh * Rn * Tn, xb = (size_t)b * Rn * Tn;
    for (int e = threadIdx.x; e < Rn * Tn; e += 256) g_feats[base + e] = x[xb + e];
}

__global__ void k_agg()
{
    int bh = blockIdx.x;
    if (!g_flag[bh]) return;
    float gt = g_gate[bh];
    size_t base = (size_t)bh * Rn * Tn;
    int tid = threadIdx.x;
    for (int r = 0; r < Rn; r++) {
        int cnt = g_spcnt[bh * Rn + r];
        int sb  = (bh * Rn + r) * 8;
        for (int t = tid; t < Tn; t += 256) {
            float a = 0.f;
            for (int i = 0; i < cnt; i++)
                a = fmaf(g_spval[sb + i],
                         g_feats[base + (size_t)g_spcol[sb + i] * Tn + t], a);
            g_agg[base + (size_t)r * Tn + t] = a * gt;
        }
    }
}

__global__ void k_gcn(const float* __restrict__ W, const float* __restrict__ bias)
{
    int bh = blockIdx.x;
    if (!g_flag[bh]) return;
    size_t base = (size_t)bh * Rn * Tn;
    for (int e = threadIdx.x; e < Rn * Tn; e += 256) {
        int r = e >> 8, t = e & 255;
        float acc = bias[t];
        const float* ag = g_agg + base + (size_t)r * Tn;
        const float* wr = W + (size_t)t * Tn;
        for (int u = 0; u < Tn; u++) acc = fmaf(ag[u], wr[u], acc);
        g_feats[base + e] = fmaxf(acc, 0.f) + g_feats[base + e];
    }
}

// ---------------- K5: fusion + pool + MLP head ----------------------------
__global__ void k_head(const float* __restrict__ x,
                       const float* __restrict__ fw, const float* __restrict__ fb,
                       const float* __restrict__ W1, const float* __restrict__ b1,
                       const float* __restrict__ W2, const float* __restrict__ b2,
                       const float* __restrict__ W3, const float* __restrict__ b3,
                       float* __restrict__ out)
{
    int b = blockIdx.x;
    int tid = threadIdx.x, lane = tid & 31, w = tid >> 5;
    __shared__ float pooled[132], sh1[64], sh2[16];
    __shared__ float swf[8];
    __shared__ int   sfl[8];
    if (tid < 8) { swf[tid] = fw[tid]; sfl[tid] = g_flag[b * 8 + tid]; }
    __syncthreads();
    float meanS = g_S[256], fbv = *fb;

    for (int r = w; r < Rn; r += 8) {
        const float* xr = x + ((size_t)b * Rn + r) * Tn;
        float sx = 0.f;
        for (int t = lane; t < Tn; t += 32) sx += xr[t];
        #pragma unroll
        for (int o = 16; o; o >>= 1) sx += __shfl_xor_sync(~0u, sx, o);
        float mx = sx * (1.f / 256.f);
        float acc = fbv;
        #pragma unroll
        for (int h = 0; h < 8; h++) {
            if (sfl[h]) {
                const float* fr = g_feats + ((size_t)(b * 8 + h) * Rn + r) * Tn;
                float sf = 0.f;
                for (int t = lane; t < Tn; t += 32) sf += fr[t];
                #pragma unroll
                for (int o = 16; o; o >>= 1) sf += __shfl_xor_sync(~0u, sf, o);
                acc = fmaf(swf[h], sf * (1.f / 256.f), acc);
            } else {
                acc = fmaf(swf[h], mx + meanS, acc);   // closed form: feats = x + S
            }
        }
        if (lane == 0) pooled[r] = acc;
    }
    __syncthreads();
    if (tid < 64) {
        float a = b1[tid];
        for (int r = 0; r < Rn; r++) a = fmaf(W1[tid * Rn + r], pooled[r], a);
        sh1[tid] = fmaxf(a, 0.f);
    }
    __syncthreads();
    if (tid < 16) {
        float a = b2[tid];
        #pragma unroll
        for (int j = 0; j < 64; j++) a = fmaf(W2[tid * 64 + j], sh1[j], a);
        sh2[tid] = fmaxf(a, 0.f);
    }
    __syncthreads();
    if (tid < 5) {
        float a = b3[tid];
        #pragma unroll
        for (int j = 0; j < 16; j++) a = fmaf(W3[tid * 16 + j], sh2[j], a);
        out[b * 5 + tid] = fmaxf(a, 0.f);
    }
}

// ---------------- launch ---------------------------------------------------
extern "C" void kernel_launch(void* const* d_in, const int* in_sizes, int n_in,
                              void* d_out, int out_size)
{
    const float* x    = (const float*)d_in[0];
    const float* Wq   = (const float*)d_in[1];
    const float* bq   = (const float*)d_in[2];
    const float* Wk   = (const float*)d_in[3];
    const float* bk   = (const float*)d_in[4];
    const float* thr  = (const float*)d_in[5];
    const float* seW1 = (const float*)d_in[6];
    const float* seb1 = (const float*)d_in[7];
    const float* seW2 = (const float*)d_in[8];
    const float* seb2 = (const float*)d_in[9];
    const float* gcnW = (const float*)d_in[10];
    const float* gcnb = (const float*)d_in[11];
    const float* fw   = (const float*)d_in[12];
    const float* fb   = (const float*)d_in[13];
    const float* W1   = (const float*)d_in[14];
    const float* b1   = (const float*)d_in[15];
    const float* W2   = (const float*)d_in[16];
    const float* b2   = (const float*)d_in[17];
    const float* W3   = (const float*)d_in[18];
    const float* b3   = (const float*)d_in[19];
    float* out = (float*)d_out;

    const size_t SMEM_ATTN = (size_t)(2 * Rn * SQS + Rn * RELS) * sizeof(float);
    cudaFuncSetAttribute(k_attn, cudaFuncAttributeMaxDynamicSharedMemorySize,
                         (int)SMEM_ATTN);

    dim3 g1(Mn / 64, NQK / 64);
    k_qkproj<<<g1, 256>>>(x, Wq, bq, Wk, bk);
    k_attn<<<BHn, 256, SMEM_ATTN>>>(thr);
    k_prep<<<1, 256>>>(gcnb);
    k_gate<<<Bn, 32>>>(seW1, seb1, seW2, seb2);
    k_finit<<<BHn, 256>>>(x);
    for (int i = 0; i < 8; i++) {
        k_agg<<<BHn, 256>>>();
        k_gcn<<<BHn, 256>>>(gcnW + (size_t)i * 256 * 256, gcnb + i * 256);
    }
    k_head<<<Bn, 256>>>(x, fw, fb, W1, b1, W2, b2, W3, b3, out);
}

// round 2
// speedup vs baseline: 1.1632x; 1.1632x over previous
#include <cuda_runtime.h>
#include <math.h>

#define Bn   128
#define Hn   8
#define Rn   130
#define Tn   256
#define Qd   32
#define BHn  (Bn*Hn)     /* 1024 */
#define Mn   (Bn*Rn)     /* 16640 */
#define NQK  512

// ---------------- device scratch (no allocations allowed) ----------------
__device__ float g_qk[(size_t)Mn*NQK];            // q|k projections, [M,512]
__device__ float g_feats[(size_t)BHn*Rn*Tn];      // GCN features (flagged heads only)
__device__ float g_agg[(size_t)BHn*Rn*Tn];        // sparse A @ feats scratch
__device__ float g_spval[BHn*Rn*8];               // sparse A values (pre-gate)
__device__ int   g_spcol[BHn*Rn*8];               // sparse A column indices
__device__ int   g_spcnt[BHn*Rn];                 // nnz per row (6 or 7)
__device__ float g_gap[BHn];                      // sum of rel per (b,h)
__device__ float g_maxA[BHn];                     // max kept rel value per (b,h)
__device__ float g_gate[BHn];                     // SE gate (0 or 1)
__device__ int   g_flag[BHn];                     // gate!=0 && maxA>0
__device__ float g_S[Tn+1];                       // S[t]=sum_i relu(gcn_b[i][t]); S[256]=mean

// ---------------- dummy (ncu alignment: puts k_qkproj at capture slot) ----
__global__ void k_nop() {}

// ---------------- K1: qk = x @ [Wq;Wk]^T + [bq;bk] -----------------------
// M=16640, N=512, K=256. 128x128 tile, BK=16, 256 threads, 8x8 microtile.
__global__ void __launch_bounds__(256, 2)
k_qkproj(const float* __restrict__ x,
         const float* __restrict__ Wq, const float* __restrict__ bq,
         const float* __restrict__ Wk, const float* __restrict__ bk)
{
    __shared__ float As[16][132];
    __shared__ float Bs[16][132];
    int tid = threadIdx.x;
    int m0 = blockIdx.x * 128, n0 = blockIdx.y * 128;

    int lrow = tid >> 1;            // 0..127
    int lkc  = (tid & 1) * 8;       // 0 or 8

    int tm = (tid >> 4) << 3;       // 0..120 step 8
    int tn = (tid & 15) << 3;

    float acc[8][8] = {};

    const float* arow = x + (size_t)(m0 + lrow) * 256;
    int ng = n0 + lrow;
    const float* brow = (ng < 256) ? (Wq + (size_t)ng * 256)
                                   : (Wk + (size_t)(ng - 256) * 256);

    for (int k0 = 0; k0 < 256; k0 += 16) {
        float4 a0 = *(const float4*)(arow + k0 + lkc);
        float4 a1 = *(const float4*)(arow + k0 + lkc + 4);
        float4 b0 = *(const float4*)(brow + k0 + lkc);
        float4 b1 = *(const float4*)(brow + k0 + lkc + 4);
        As[lkc+0][lrow] = a0.x; As[lkc+1][lrow] = a0.y;
        As[lkc+2][lrow] = a0.z; As[lkc+3][lrow] = a0.w;
        As[lkc+4][lrow] = a1.x; As[lkc+5][lrow] = a1.y;
        As[lkc+6][lrow] = a1.z; As[lkc+7][lrow] = a1.w;
        Bs[lkc+0][lrow] = b0.x; Bs[lkc+1][lrow] = b0.y;
        Bs[lkc+2][lrow] = b0.z; Bs[lkc+3][lrow] = b0.w;
        Bs[lkc+4][lrow] = b1.x; Bs[lkc+5][lrow] = b1.y;
        Bs[lkc+6][lrow] = b1.z; Bs[lkc+7][lrow] = b1.w;
        __syncthreads();
        #pragma unroll
        for (int kk = 0; kk < 16; kk++) {
            float4 av0 = *(const float4*)&As[kk][tm];
            float4 av1 = *(const float4*)&As[kk][tm + 4];
            float4 bv0 = *(const float4*)&Bs[kk][tn];
            float4 bv1 = *(const float4*)&Bs[kk][tn + 4];
            float a[8] = {av0.x, av0.y, av0.z, av0.w, av1.x, av1.y, av1.z, av1.w};
            float bb[8] = {bv0.x, bv0.y, bv0.z, bv0.w, bv1.x, bv1.y, bv1.z, bv1.w};
            #pragma unroll
            for (int i = 0; i < 8; i++)
                #pragma unroll
                for (int j = 0; j < 8; j++)
                    acc[i][j] = fmaf(a[i], bb[j], acc[i][j]);
        }
        __syncthreads();
    }

    float bias[8];
    #pragma unroll
    for (int j = 0; j < 8; j++) {
        int n = n0 + tn + j;
        bias[j] = (n < 256) ? bq[n] : bk[n - 256];
    }
    #pragma unroll
    for (int i = 0; i < 8; i++) {
        float* orow = g_qk + (size_t)(m0 + tm + i) * NQK + n0 + tn;
        float4 o0 = make_float4(acc[i][0]+bias[0], acc[i][1]+bias[1],
                                acc[i][2]+bias[2], acc[i][3]+bias[3]);
        float4 o1 = make_float4(acc[i][4]+bias[4], acc[i][5]+bias[5],
                                acc[i][6]+bias[6], acc[i][7]+bias[7]);
        *(float4*)orow = o0;
        *(float4*)(orow + 4) = o1;
    }
}

// ---------------- K2: rel -> softmax -> relu-thr -> ranks/sparse ---------
#define SQS  36    /* padded row stride for q/k (mult of 4 -> LDS.128) */
#define RELS 132   /* padded row stride for rel */
__global__ void k_attn(const float* __restrict__ thr_p)
{
    extern __shared__ float sm[];
    float* sq   = sm;                   // 132*36
    float* sk   = sm +     132 * SQS;   // 132*36
    float* srel = sm + 2 * 132 * SQS;   // 132*132
    __shared__ float s_gap[8], s_max[8];

    int bh = blockIdx.x, b = bh >> 3, h = bh & 7;
    int tid = threadIdx.x, lane = tid & 31, w = tid >> 5;
    const float thr = *thr_p;

    // load q,k (rows 130,131 zero-padded)
    for (int e = tid; e < 132 * Qd; e += 256) {
        int r = e >> 5, i = e & 31;
        float qv = 0.f, kv = 0.f;
        if (r < Rn) {
            size_t rowb = (size_t)(b * Rn + r) * NQK + h * 32;
            qv = g_qk[rowb + i];
            kv = g_qk[rowb + 256 + i];
        }
        sq[r * SQS + i] = qv;
        sk[r * SQS + i] = kv;
    }
    __syncthreads();

    // rel = q k^T / sqrt(32): 33x33 tiles of 4x4, float4 LDS
    for (int e = tid; e < 33 * 33; e += 256) {
        int r0 = (e / 33) * 4, s0 = (e % 33) * 4;
        float acc[4][4] = {};
        #pragma unroll
        for (int i4 = 0; i4 < 32; i4 += 4) {
            float4 qv[4], kv[4];
            #pragma unroll
            for (int j = 0; j < 4; j++) {
                qv[j] = *(const float4*)&sq[(r0 + j) * SQS + i4];
                kv[j] = *(const float4*)&sk[(s0 + j) * SQS + i4];
            }
            #pragma unroll
            for (int i = 0; i < 4; i++)
                #pragma unroll
                for (int j = 0; j < 4; j++) {
                    acc[i][j] = fmaf(qv[i].x, kv[j].x, acc[i][j]);
                    acc[i][j] = fmaf(qv[i].y, kv[j].y, acc[i][j]);
                    acc[i][j] = fmaf(qv[i].z, kv[j].z, acc[i][j]);
                    acc[i][j] = fmaf(qv[i].w, kv[j].w, acc[i][j]);
                }
        }
        const float sc = 0.17677669529663687f;  // 1/sqrt(32)
        #pragma unroll
        for (int i = 0; i < 4; i++) {
            float4 o = make_float4(acc[i][0]*sc, acc[i][1]*sc, acc[i][2]*sc, acc[i][3]*sc);
            *(float4*)&srel[(r0 + i) * RELS + s0] = o;
        }
    }
    __syncthreads();

    float gapAcc = 0.f, maxAcc = 0.f;
    for (int r = w; r < Rn; r += 8) {
        float* row = srel + r * RELS;
        float mval = -1e30f;
        for (int j = lane; j < Rn; j += 32) mval = fmaxf(mval, row[j]);
        #pragma unroll
        for (int o = 16; o; o >>= 1) mval = fmaxf(mval, __shfl_xor_sync(~0u, mval, o));
        float se = 0.f;
        for (int j = lane; j < Rn; j += 32) {
            float e = __expf(row[j] - mval); row[j] = e; se += e;
        }
        #pragma unroll
        for (int o = 16; o; o >>= 1) se += __shfl_xor_sync(~0u, se, o);
        float rinv = 1.f / se;
        float gs = 0.f;
        for (int j = lane; j < Rn; j += 32) {
            float v = fmaxf(fmaf(row[j], rinv, -thr), 0.f);
            row[j] = v; gs += v;
        }
        #pragma unroll
        for (int o = 16; o; o >>= 1) gs += __shfl_xor_sync(~0u, gs, o);
        __syncwarp();

        // ranks (stable descending) of columns {0, 4..8}
        const int cols0[6] = {0, 4, 5, 6, 7, 8};
        float vc[6];
        #pragma unroll
        for (int c = 0; c < 6; c++) vc[c] = row[cols0[c]];
        int gt[6] = {0,0,0,0,0,0}, eqb[6] = {0,0,0,0,0,0};
        for (int j0 = 0; j0 < Rn; j0 += 32) {
            int j = j0 + lane; bool val = (j < Rn);
            float vj = val ? row[j] : 0.f;
            #pragma unroll
            for (int c = 0; c < 6; c++) {
                unsigned bgt = __ballot_sync(~0u, val && (vj > vc[c]));
                unsigned beq = __ballot_sync(~0u, val && (vj == vc[c]) && (j < cols0[c]));
                gt[c]  += __popc(bgt);
                eqb[c] += __popc(beq);
            }
        }
        if (lane == 0) {
            gapAcc += gs;
            int pos[7]; int cnt = 0;
            #pragma unroll
            for (int c = 0; c < 6; c++) pos[cnt++] = gt[c] + eqb[c];
            bool hasR = false;
            #pragma unroll
            for (int c = 0; c < 6; c++) if (pos[c] == r) hasR = true;
            if (!hasR) pos[cnt++] = r;
            int base = (bh * Rn + r) * 8;
            float rmax = 0.f;
            for (int c = 0; c < cnt; c++) {
                float v = row[pos[c]];
                g_spcol[base + c] = pos[c];
                g_spval[base + c] = v;
                rmax = fmaxf(rmax, v);
            }
            g_spcnt[bh * Rn + r] = cnt;
            maxAcc = fmaxf(maxAcc, rmax);
        }
    }
    if (lane == 0) { s_gap[w] = gapAcc; s_max[w] = maxAcc; }
    __syncthreads();
    if (tid == 0) {
        float g = 0.f, mx = 0.f;
        #pragma unroll
        for (int i = 0; i < 8; i++) { g += s_gap[i]; mx = fmaxf(mx, s_max[i]); }
        g_gap[bh] = g; g_maxA[bh] = mx;
    }
}

// ---------------- K3: SE gate + flags -------------------------------------
__global__ void k_gate(const float* __restrict__ seW1, const float* __restrict__ seb1,
                       const float* __restrict__ seW2, const float* __restrict__ seb2)
{
    int b = blockIdx.x;
    if (threadIdx.x) return;
    float g[8];
    #pragma unroll
    for (int h = 0; h < 8; h++) g[h] = g_gap[b * 8 + h] * (1.f / 16900.f);
    float hd[4];
    #pragma unroll
    for (int j = 0; j < 4; j++) {
        float a = seb1[j];
        #pragma unroll
        for (int h = 0; h < 8; h++) a = fmaf(seW1[j * 8 + h], g[h], a);
        hd[j] = fmaxf(a, 0.f);
    }
    #pragma unroll
    for (int i = 0; i < 8; i++) {
        float z = seb2[i];
        #pragma unroll
        for (int j = 0; j < 4; j++) z = fmaf(seW2[i * 4 + j], hd[j], z);
        float gt = floorf(1.f / (1.f + expf(-z)));   // .long() truncation
        g_gate[b * 8 + i] = gt;
        g_flag[b * 8 + i] = (gt != 0.f) && (g_maxA[b * 8 + i] > 0.f);
    }
}

// ---------------- Kprep: S[t] = sum_i relu(gcn_b[i][t]) -------------------
__global__ void k_prep(const float* __restrict__ gcn_b)
{
    __shared__ float red[256];
    int t = threadIdx.x;
    float s = 0.f;
    #pragma unroll
    for (int i = 0; i < 8; i++) s += fmaxf(gcn_b[i * 256 + t], 0.f);
    g_S[t] = s;
    red[t] = s; __syncthreads();
    for (int o = 128; o; o >>= 1) { if (t < o) red[t] += red[t + o]; __syncthreads(); }
    if (t == 0) g_S[256] = red[0] * (1.f / 256.f);
}

// ---------------- GCN: all 8 layers, one block per (b,h), flag-guarded ----
__global__ void k_gcnall(const float* __restrict__ x,
                         const float* __restrict__ gcnW, const float* __restrict__ gcnb)
{
    int bh = blockIdx.x;
    if (!g_flag[bh]) return;
    int b = bh >> 3;
    float gt = g_gate[bh];
    size_t base = (size_t)bh * Rn * Tn;
    const float* xb = x + (size_t)b * Rn * Tn;

    for (int e = threadIdx.x; e < Rn * Tn; e += 256) g_feats[base + e] = xb[e];
    __syncthreads();

    for (int L = 0; L < 8; L++) {
        const float* W    = gcnW + (size_t)L * Tn * Tn;
        const float* bias = gcnb + L * Tn;
        for (int e = threadIdx.x; e < Rn * Tn; e += 256) {
            int r = e >> 8, t = e & 255;
            int cnt = g_spcnt[bh * Rn + r];
            int sb  = (bh * Rn + r) * 8;
            float a = 0.f;
            for (int i = 0; i < cnt; i++)
                a = fmaf(g_spval[sb + i],
                         g_feats[base + (size_t)g_spcol[sb + i] * Tn + t], a);
            g_agg[base + e] = a * gt;
        }
        __syncthreads();
        for (int e = threadIdx.x; e < Rn * Tn; e += 256) {
            int r = e >> 8, t = e & 255;
            float acc = bias[t];
            const float* ag = g_agg + base + (size_t)r * Tn;
            const float* wr = W + (size_t)t * Tn;
            for (int u = 0; u < Tn; u++) acc = fmaf(ag[u], wr[u], acc);
            g_feats[base + e] = fmaxf(acc, 0.f) + g_feats[base + e];
        }
        __syncthreads();
    }
}

// ---------------- K5: fusion + pool + MLP head ----------------------------
__global__ void k_head(const float* __restrict__ x,
                       const float* __restrict__ fw, const float* __restrict__ fb,
                       const float* __restrict__ W1, const float* __restrict__ b1,
                       const float* __restrict__ W2, const float* __restrict__ b2,
                       const float* __restrict__ W3, const float* __restrict__ b3,
                       float* __restrict__ out)
{
    int b = blockIdx.x;
    int tid = threadIdx.x, lane = tid & 31, w = tid >> 5;
    __shared__ float pooled[132], sh1[64], sh2[16];
    __shared__ float swf[8];
    __shared__ int   sfl[8];
    if (tid < 8) { swf[tid] = fw[tid]; sfl[tid] = g_flag[b * 8 + tid]; }
    __syncthreads();
    float meanS = g_S[256], fbv = *fb;

    for (int r = w; r < Rn; r += 8) {
        const float* xr = x + ((size_t)b * Rn + r) * Tn;
        float sx = 0.f;
        for (int t = lane; t < Tn; t += 32) sx += xr[t];
        #pragma unroll
        for (int o = 16; o; o >>= 1) sx += __shfl_xor_sync(~0u, sx, o);
        float mx = sx * (1.f / 256.f);
        float acc = fbv;
        #pragma unroll
        for (int h = 0; h < 8; h++) {
            if (sfl[h]) {
                const float* fr = g_feats + ((size_t)(b * 8 + h) * Rn + r) * Tn;
                float sf = 0.f;
                for (int t = lane; t < Tn; t += 32) sf += fr[t];
                #pragma unroll
                for (int o = 16; o; o >>= 1) sf += __shfl_xor_sync(~0u, sf, o);
                acc = fmaf(swf[h], sf * (1.f / 256.f), acc);
            } else {
                acc = fmaf(swf[h], mx + meanS, acc);   // closed form: feats = x + S
            }
        }
        if (lane == 0) pooled[r] = acc;
    }
    __syncthreads();
    if (tid < 64) {
        float a = b1[tid];
        for (int r = 0; r < Rn; r++) a = fmaf(W1[tid * Rn + r], pooled[r], a);
        sh1[tid] = fmaxf(a, 0.f);
    }
    __syncthreads();
    if (tid < 16) {
        float a = b2[tid];
        #pragma unroll
        for (int j = 0; j < 64; j++) a = fmaf(W2[tid * 64 + j], sh1[j], a);
        sh2[tid] = fmaxf(a, 0.f);
    }
    __syncthreads();
    if (tid < 5) {
        float a = b3[tid];
        #pragma unroll
        for (int j = 0; j < 16; j++) a = fmaf(W3[tid * 16 + j], sh2[j], a);
        out[b * 5 + tid] = fmaxf(a, 0.f);
    }
}

// ---------------- launch ---------------------------------------------------
extern "C" void kernel_launch(void* const* d_in, const int* in_sizes, int n_in,
                              void* d_out, int out_size)
{
    const float* x    = (const float*)d_in[0];
    const float* Wq   = (const float*)d_in[1];
    const float* bq   = (const float*)d_in[2];
    const float* Wk   = (const float*)d_in[3];
    const float* bk   = (const float*)d_in[4];
    const float* thr  = (const float*)d_in[5];
    const float* seW1 = (const float*)d_in[6];
    const float* seb1 = (const float*)d_in[7];
    const float* seW2 = (const float*)d_in[8];
    const float* seb2 = (const float*)d_in[9];
    const float* gcnW = (const float*)d_in[10];
    const float* gcnb = (const float*)d_in[11];
    const float* fw   = (const float*)d_in[12];
    const float* fb   = (const float*)d_in[13];
    const float* W1   = (const float*)d_in[14];
    const float* b1   = (const float*)d_in[15];
    const float* W2   = (const float*)d_in[16];
    const float* b2   = (const float*)d_in[17];
    const float* W3   = (const float*)d_in[18];
    const float* b3   = (const float*)d_in[19];
    float* out = (float*)d_out;

    const size_t SMEM_ATTN = (size_t)(2 * 132 * SQS + 132 * RELS) * sizeof(float);
    cudaFuncSetAttribute(k_attn, cudaFuncAttributeMaxDynamicSharedMemorySize,
                         (int)SMEM_ATTN);

    // launches 1-5 (cheap) so ncu's "-s 5 -c 1" captures k_qkproj at slot 6
    k_prep<<<1, 256>>>(gcnb);
    k_nop<<<1, 32>>>();
    k_nop<<<1, 32>>>();
    k_nop<<<1, 32>>>();
    k_nop<<<1, 32>>>();

    dim3 g1(Mn / 128, NQK / 128);
    k_qkproj<<<g1, 256>>>(x, Wq, bq, Wk, bk);
    k_attn<<<BHn, 256, SMEM_ATTN>>>(thr);
    k_gate<<<Bn, 32>>>(seW1, seb1, seW2, seb2);
    k_gcnall<<<BHn, 256>>>(x, gcnW, gcnb);
    k_head<<<Bn, 256>>>(x, fw, fb, W1, b1, W2, b2, W3, b3, out);
}

// round 3
// speedup vs baseline: 1.2975x; 1.1155x over previous
#include <cuda_runtime.h>
#include <mma.h>
#include <math.h>

using namespace nvcuda;

#define Bn   128
#define Hn   8
#define Rn   130
#define Tn   256
#define Qd   32
#define BHn  (Bn*Hn)     /* 1024 */
#define Mn   (Bn*Rn)     /* 16640 */
#define NQK  512

// ---------------- device scratch (no allocations allowed) ----------------
__device__ float g_qk[(size_t)Mn*NQK];            // q|k projections (NO bias), [M,512]
__device__ float g_feats[(size_t)BHn*Rn*Tn];      // GCN features (flagged heads only)
__device__ float g_agg[(size_t)BHn*Rn*Tn];        // sparse A @ feats scratch
__device__ float g_spval[BHn*Rn*8];               // sparse A values (pre-gate)
__device__ int   g_spcol[BHn*Rn*8];               // sparse A column indices
__device__ int   g_spcnt[BHn*Rn];                 // nnz per row (6 or 7)
__device__ float g_gap[BHn];                      // sum of rel per (b,h)
__device__ float g_maxA[BHn];                     // max kept rel value per (b,h)
__device__ float g_gate[BHn];                     // SE gate (0 or 1)
__device__ int   g_flag[BHn];                     // gate!=0 && maxA>0
__device__ float g_S[Tn+1];                       // S[t]=sum_i relu(gcn_b[i][t]); S[256]=mean

__global__ void k_nop() {}

// ---------------- K1: qk = x @ [Wq;Wk]^T  (tf32 HMMA) ---------------------
// M=16640, N=512, K=256. Block tile 128x128, BK=32, 8 warps, warp tile 64x32.
#define XPAD 40
__global__ void __launch_bounds__(256)
k_qkproj(const float* __restrict__ x,
         const float* __restrict__ Wq, const float* __restrict__ Wk)
{
    __shared__ float Xs[128 * XPAD];
    __shared__ float Ws[128 * XPAD];

    int tid = threadIdx.x;
    int wid = tid >> 5;
    int m0 = blockIdx.x * 128, n0 = blockIdx.y * 128;
    int wm = wid >> 2;          // 0..1 : 64-row slice
    int wn = wid & 3;           // 0..3 : 32-col slice

    // W base: blocks are wholly inside Wq (n0<256) or Wk
    const float* Wbase = (n0 < 256) ? (Wq + (size_t)n0 * 256)
                                    : (Wk + (size_t)(n0 - 256) * 256);
    const float* Xbase = x + (size_t)m0 * 256;

    wmma::fragment<wmma::accumulator, 16, 16, 8, float> acc[4][2];
    #pragma unroll
    for (int i = 0; i < 4; i++)
        #pragma unroll
        for (int j = 0; j < 2; j++)
            wmma::fill_fragment(acc[i][j], 0.0f);

    for (int k0 = 0; k0 < 256; k0 += 32) {
        // load 128x32 fp32 tiles (4 float4 per thread each)
        #pragma unroll
        for (int i = 0; i < 4; i++) {
            int idx = tid + i * 256;          // 0..1023
            int row = idx >> 3;
            int c4  = (idx & 7) * 4;
            *(float4*)&Xs[row * XPAD + c4] =
                *(const float4*)(Xbase + (size_t)row * 256 + k0 + c4);
            *(float4*)&Ws[row * XPAD + c4] =
                *(const float4*)(Wbase + (size_t)row * 256 + k0 + c4);
        }
        __syncthreads();

        #pragma unroll
        for (int kk = 0; kk < 32; kk += 8) {
            wmma::fragment<wmma::matrix_a, 16, 16, 8, wmma::precision::tf32, wmma::row_major> af[4];
            wmma::fragment<wmma::matrix_b, 16, 16, 8, wmma::precision::tf32, wmma::col_major> bf[2];
            #pragma unroll
            for (int i = 0; i < 4; i++) {
                wmma::load_matrix_sync(af[i], &Xs[(wm * 64 + i * 16) * XPAD + kk], XPAD);
                #pragma unroll
                for (int e = 0; e < af[i].num_elements; e++)
                    af[i].x[e] = wmma::__float_to_tf32(af[i].x[e]);
            }
            #pragma unroll
            for (int j = 0; j < 2; j++) {
                // col_major matrix_b: element (k,n) at ptr[n*ld + k]
                wmma::load_matrix_sync(bf[j], &Ws[(wn * 32 + j * 16) * XPAD + kk], XPAD);
                #pragma unroll
                for (int e = 0; e < bf[j].num_elements; e++)
                    bf[j].x[e] = wmma::__float_to_tf32(bf[j].x[e]);
            }
            #pragma unroll
            for (int i = 0; i < 4; i++)
                #pragma unroll
                for (int j = 0; j < 2; j++)
                    wmma::mma_sync(acc[i][j], af[i], bf[j], acc[i][j]);
        }
        __syncthreads();
    }

    #pragma unroll
    for (int i = 0; i < 4; i++)
        #pragma unroll
        for (int j = 0; j < 2; j++) {
            float* dst = g_qk + (size_t)(m0 + wm * 64 + i * 16) * NQK
                              + n0 + wn * 32 + j * 16;
            wmma::store_matrix_sync(dst, acc[i][j], NQK, wmma::mem_row_major);
        }
}

// ---------------- K2: rel -> softmax -> relu-thr -> ranks/sparse ---------
#define SQS  36    /* padded row stride for q/k (mult of 4 -> LDS.128) */
#define RELS 132   /* padded row stride for rel */
__global__ void k_attn(const float* __restrict__ thr_p,
                       const float* __restrict__ bq, const float* __restrict__ bk)
{
    extern __shared__ float sm[];
    float* sq   = sm;                   // 132*36
    float* sk   = sm +     132 * SQS;   // 132*36
    float* srel = sm + 2 * 132 * SQS;   // 132*132
    __shared__ float s_gap[8], s_max[8];

    int bh = blockIdx.x, b = bh >> 3, h = bh & 7;
    int tid = threadIdx.x, lane = tid & 31, w = tid >> 5;
    const float thr = *thr_p;

    // load q,k + bias (rows 130,131 zero-padded)
    for (int e = tid; e < 132 * Qd; e += 256) {
        int r = e >> 5, i = e & 31;
        float qv = 0.f, kv = 0.f;
        if (r < Rn) {
            size_t rowb = (size_t)(b * Rn + r) * NQK + h * 32;
            qv = g_qk[rowb + i]       + bq[h * 32 + i];
            kv = g_qk[rowb + 256 + i] + bk[h * 32 + i];
        }
        sq[r * SQS + i] = qv;
        sk[r * SQS + i] = kv;
    }
    __syncthreads();

    // rel = q k^T / sqrt(32): 33x33 tiles of 4x4, float4 LDS
    for (int e = tid; e < 33 * 33; e += 256) {
        int r0 = (e / 33) * 4, s0 = (e % 33) * 4;
        float acc[4][4] = {};
        #pragma unroll
        for (int i4 = 0; i4 < 32; i4 += 4) {
            float4 qv[4], kv[4];
            #pragma unroll
            for (int j = 0; j < 4; j++) {
                qv[j] = *(const float4*)&sq[(r0 + j) * SQS + i4];
                kv[j] = *(const float4*)&sk[(s0 + j) * SQS + i4];
            }
            #pragma unroll
            for (int i = 0; i < 4; i++)
                #pragma unroll
                for (int j = 0; j < 4; j++) {
                    acc[i][j] = fmaf(qv[i].x, kv[j].x, acc[i][j]);
                    acc[i][j] = fmaf(qv[i].y, kv[j].y, acc[i][j]);
                    acc[i][j] = fmaf(qv[i].z, kv[j].z, acc[i][j]);
                    acc[i][j] = fmaf(qv[i].w, kv[j].w, acc[i][j]);
                }
        }
        const float sc = 0.17677669529663687f;  // 1/sqrt(32)
        #pragma unroll
        for (int i = 0; i < 4; i++) {
            float4 o = make_float4(acc[i][0]*sc, acc[i][1]*sc, acc[i][2]*sc, acc[i][3]*sc);
            *(float4*)&srel[(r0 + i) * RELS + s0] = o;
        }
    }
    __syncthreads();

    float gapAcc = 0.f, maxAcc = 0.f;
    for (int r = w; r < Rn; r += 8) {
        float* row = srel + r * RELS;
        float mval = -1e30f;
        for (int j = lane; j < Rn; j += 32) mval = fmaxf(mval, row[j]);
        #pragma unroll
        for (int o = 16; o; o >>= 1) mval = fmaxf(mval, __shfl_xor_sync(~0u, mval, o));
        float se = 0.f;
        for (int j = lane; j < Rn; j += 32) {
            float e = __expf(row[j] - mval); row[j] = e; se += e;
        }
        #pragma unroll
        for (int o = 16; o; o >>= 1) se += __shfl_xor_sync(~0u, se, o);
        float rinv = 1.f / se;
        float gs = 0.f;
        for (int j = lane; j < Rn; j += 32) {
            float v = fmaxf(fmaf(row[j], rinv, -thr), 0.f);
            row[j] = v; gs += v;
        }
        #pragma unroll
        for (int o = 16; o; o >>= 1) gs += __shfl_xor_sync(~0u, gs, o);
        __syncwarp();

        // ranks (stable descending) of columns {0, 4..8}
        const int cols0[6] = {0, 4, 5, 6, 7, 8};
        float vc[6];
        #pragma unroll
        for (int c = 0; c < 6; c++) vc[c] = row[cols0[c]];
        int gt[6] = {0,0,0,0,0,0}, eqb[6] = {0,0,0,0,0,0};
        for (int j0 = 0; j0 < Rn; j0 += 32) {
            int j = j0 + lane; bool val = (j < Rn);
            float vj = val ? row[j] : 0.f;
            #pragma unroll
            for (int c = 0; c < 6; c++) {
                unsigned bgt = __ballot_sync(~0u, val && (vj > vc[c]));
                unsigned beq = __ballot_sync(~0u, val && (vj == vc[c]) && (j < cols0[c]));
                gt[c]  += __popc(bgt);
                eqb[c] += __popc(beq);
            }
        }
        if (lane == 0) {
            gapAcc += gs;
            int pos[7]; int cnt = 0;
            #pragma unroll
            for (int c = 0; c < 6; c++) pos[cnt++] = gt[c] + eqb[c];
            bool hasR = false;
            #pragma unroll
            for (int c = 0; c < 6; c++) if (pos[c] == r) hasR = true;
            if (!hasR) pos[cnt++] = r;
            int base = (bh * Rn + r) * 8;
            float rmax = 0.f;
            for (int c = 0; c < cnt; c++) {
                float v = row[pos[c]];
                g_spcol[base + c] = pos[c];
                g_spval[base + c] = v;
                rmax = fmaxf(rmax, v);
            }
            g_spcnt[bh * Rn + r] = cnt;
            maxAcc = fmaxf(maxAcc, rmax);
        }
    }
    if (lane == 0) { s_gap[w] = gapAcc; s_max[w] = maxAcc; }
    __syncthreads();
    if (tid == 0) {
        float g = 0.f, mx = 0.f;
        #pragma unroll
        for (int i = 0; i < 8; i++) { g += s_gap[i]; mx = fmaxf(mx, s_max[i]); }
        g_gap[bh] = g; g_maxA[bh] = mx;
    }
}

// ---------------- K3: SE gate + flags -------------------------------------
__global__ void k_gate(const float* __restrict__ seW1, const float* __restrict__ seb1,
                       const float* __restrict__ seW2, const float* __restrict__ seb2)
{
    int b = blockIdx.x;
    if (threadIdx.x) return;
    float g[8];
    #pragma unroll
    for (int h = 0; h < 8; h++) g[h] = g_gap[b * 8 + h] * (1.f / 16900.f);
    float hd[4];
    #pragma unroll
    for (int j = 0; j < 4; j++) {
        float a = seb1[j];
        #pragma unroll
        for (int h = 0; h < 8; h++) a = fmaf(seW1[j * 8 + h], g[h], a);
        hd[j] = fmaxf(a, 0.f);
    }
    #pragma unroll
    for (int i = 0; i < 8; i++) {
        float z = seb2[i];
        #pragma unroll
        for (int j = 0; j < 4; j++) z = fmaf(seW2[i * 4 + j], hd[j], z);
        float gt = floorf(1.f / (1.f + expf(-z)));   // .long() truncation
        g_gate[b * 8 + i] = gt;
        g_flag[b * 8 + i] = (gt != 0.f) && (g_maxA[b * 8 + i] > 0.f);
    }
}

// ---------------- Kprep: S[t] = sum_i relu(gcn_b[i][t]) -------------------
__global__ void k_prep(const float* __restrict__ gcn_b)
{
    __shared__ float red[256];
    int t = threadIdx.x;
    float s = 0.f;
    #pragma unroll
    for (int i = 0; i < 8; i++) s += fmaxf(gcn_b[i * 256 + t], 0.f);
    g_S[t] = s;
    red[t] = s; __syncthreads();
    for (int o = 128; o; o >>= 1) { if (t < o) red[t] += red[t + o]; __syncthreads(); }
    if (t == 0) g_S[256] = red[0] * (1.f / 256.f);
}

// ---------------- GCN: all 8 layers, one block per (b,h), flag-guarded ----
__global__ void k_gcnall(const float* __restrict__ x,
                         const float* __restrict__ gcnW, const float* __restrict__ gcnb)
{
    int bh = blockIdx.x;
    if (!g_flag[bh]) return;
    int b = bh >> 3;
    float gt = g_gate[bh];
    size_t base = (size_t)bh * Rn * Tn;
    const float* xb = x + (size_t)b * Rn * Tn;

    for (int e = threadIdx.x; e < Rn * Tn; e += 256) g_feats[base + e] = xb[e];
    __syncthreads();

    for (int L = 0; L < 8; L++) {
        const float* W    = gcnW + (size_t)L * Tn * Tn;
        const float* bias = gcnb + L * Tn;
        for (int e = threadIdx.x; e < Rn * Tn; e += 256) {
            int r = e >> 8, t = e & 255;
            int cnt = g_spcnt[bh * Rn + r];
            int sb  = (bh * Rn + r) * 8;
            float a = 0.f;
            for (int i = 0; i < cnt; i++)
                a = fmaf(g_spval[sb + i],
                         g_feats[base + (size_t)g_spcol[sb + i] * Tn + t], a);
            g_agg[base + e] = a * gt;
        }
        __syncthreads();
        for (int e = threadIdx.x; e < Rn * Tn; e += 256) {
            int r = e >> 8, t = e & 255;
            float acc = bias[t];
            const float* ag = g_agg + base + (size_t)r * Tn;
            const float* wr = W + (size_t)t * Tn;
            for (int u = 0; u < Tn; u++) acc = fmaf(ag[u], wr[u], acc);
            g_feats[base + e] = fmaxf(acc, 0.f) + g_feats[base + e];
        }
        __syncthreads();
    }
}

// ---------------- K5: fusion + pool + MLP head ----------------------------
__global__ void k_head(const float* __restrict__ x,
                       const float* __restrict__ fw, const float* __restrict__ fb,
                       const float* __restrict__ W1, const float* __restrict__ b1,
                       const float* __restrict__ W2, const float* __restrict__ b2,
                       const float* __restrict__ W3, const float* __restrict__ b3,
                       float* __restrict__ out)
{
    int b = blockIdx.x;
    int tid = threadIdx.x, lane = tid & 31, w = tid >> 5;
    __shared__ float pooled[132], sh1[64], sh2[16];
    __shared__ float swf[8];
    __shared__ int   sfl[8];
    if (tid < 8) { swf[tid] = fw[tid]; sfl[tid] = g_flag[b * 8 + tid]; }
    __syncthreads();
    float meanS = g_S[256], fbv = *fb;

    for (int r = w; r < Rn; r += 8) {
        const float* xr = x + ((size_t)b * Rn + r) * Tn;
        float sx = 0.f;
        for (int t = lane; t < Tn; t += 32) sx += xr[t];
        #pragma unroll
        for (int o = 16; o; o >>= 1) sx += __shfl_xor_sync(~0u, sx, o);
        float mx = sx * (1.f / 256.f);
        float acc = fbv;
        #pragma unroll
        for (int h = 0; h < 8; h++) {
            if (sfl[h]) {
                const float* fr = g_feats + ((size_t)(b * 8 + h) * Rn + r) * Tn;
                float sf = 0.f;
                for (int t = lane; t < Tn; t += 32) sf += fr[t];
                #pragma unroll
                for (int o = 16; o; o >>= 1) sf += __shfl_xor_sync(~0u, sf, o);
                acc = fmaf(swf[h], sf * (1.f / 256.f), acc);
            } else {
                acc = fmaf(swf[h], mx + meanS, acc);   // closed form: feats = x + S
            }
        }
        if (lane == 0) pooled[r] = acc;
    }
    __syncthreads();
    if (tid < 64) {
        float a = b1[tid];
        for (int r = 0; r < Rn; r++) a = fmaf(W1[tid * Rn + r], pooled[r], a);
        sh1[tid] = fmaxf(a, 0.f);
    }
    __syncthreads();
    if (tid < 16) {
        float a = b2[tid];
        #pragma unroll
        for (int j = 0; j < 64; j++) a = fmaf(W2[tid * 64 + j], sh1[j], a);
        sh2[tid] = fmaxf(a, 0.f);
    }
    __syncthreads();
    if (tid < 5) {
        float a = b3[tid];
        #pragma unroll
        for (int j = 0; j < 16; j++) a = fmaf(W3[tid * 16 + j], sh2[j], a);
        out[b * 5 + tid] = fmaxf(a, 0.f);
    }
}

// ---------------- launch ---------------------------------------------------
extern "C" void kernel_launch(void* const* d_in, const int* in_sizes, int n_in,
                              void* d_out, int out_size)
{
    const float* x    = (const float*)d_in[0];
    const float* Wq   = (const float*)d_in[1];
    const float* bq   = (const float*)d_in[2];
    const float* Wk   = (const float*)d_in[3];
    const float* bk   = (const float*)d_in[4];
    const float* thr  = (const float*)d_in[5];
    const float* seW1 = (const float*)d_in[6];
    const float* seb1 = (const float*)d_in[7];
    const float* seW2 = (const float*)d_in[8];
    const float* seb2 = (const float*)d_in[9];
    const float* gcnW = (const float*)d_in[10];
    const float* gcnb = (const float*)d_in[11];
    const float* fw   = (const float*)d_in[12];
    const float* fb   = (const float*)d_in[13];
    const float* W1   = (const float*)d_in[14];
    const float* b1   = (const float*)d_in[15];
    const float* W2   = (const float*)d_in[16];
    const float* b2   = (const float*)d_in[17];
    const float* W3   = (const float*)d_in[18];
    const float* b3   = (const float*)d_in[19];
    float* out = (float*)d_out;

    const size_t SMEM_ATTN = (size_t)(2 * 132 * SQS + 132 * RELS) * sizeof(float);
    cudaFuncSetAttribute(k_attn, cudaFuncAttributeMaxDynamicSharedMemorySize,
                         (int)SMEM_ATTN);

    dim3 g1(Mn / 128, NQK / 128);
    k_qkproj<<<g1, 256>>>(x, Wq, Wk);                    // launch 1
    k_prep<<<1, 256>>>(gcnb);                            // launch 2
    k_nop<<<1, 32>>>();                                  // launch 3
    k_attn<<<BHn, 256, SMEM_ATTN>>>(thr, bq, bk);        // launch 4 <- ncu capture
    k_gate<<<Bn, 32>>>(seW1, seb1, seW2, seb2);          // launch 5
    k_gcnall<<<BHn, 256>>>(x, gcnW, gcnb);               // launch 6
    k_head<<<Bn, 256>>>(x, fw, fb, W1, b1, W2, b2, W3, b3, out);  // launch 7
}